// round 13
// baseline (speedup 1.0000x reference)
#include <cuda_runtime.h>
#include <math.h>

#define B_  32
#define L_  4096
#define D_  1024
#define D4_ (D_ / 4)           // 256 float4 per row
#define NA_ 8
#define NCHUNK 16
#define LCHUNK (L_ / NCHUNK)   // 256
#define NWA_ 4                 // warps per accum block (128 threads)
#define NPASS 2                // row passes (256 rows / 128 threads)
#define DH4_ 128               // float4 columns per D-half
#define NBA 256                // B_*NA_

// Scratch (all device globals; no allocation).
__device__ float g_part[B_ * NCHUNK * NA_ * D_];   // 16.8 MB
__device__ int   g_cnt [B_ * NCHUNK * NA_];
__device__ float g_feat[NBA * D_];                 // 1 MB   [ba][d]
__device__ float g_scal2[NBA * 2];                 // inv_cnt, seen
__device__ float g_h1p[32 * NBA * 128];            // 4 MB   [ds][ba][n]
__device__ float g_ehp[16 * NBA * 64];             // 1 MB   [ds][ba][n]

// 16-byte streaming load as two 64-bit halves (each = packed f32x2).
__device__ __forceinline__ void ldg_cs_2x64(const void* p,
                                            unsigned long long& x,
                                            unsigned long long& y)
{
    asm volatile("ld.global.cs.v2.u64 {%0, %1}, [%2];"
                 : "=l"(x), "=l"(y) : "l"(p));
}
__device__ __forceinline__ unsigned long long addf32x2(unsigned long long a,
                                                       unsigned long long b)
{
    unsigned long long r;
    asm("add.rn.f32x2 %0, %1, %2;" : "=l"(r) : "l"(a), "l"(b));
    return r;
}

// ---------------------------------------------------------------------------
// Kernel 1: masked segmented sum into per-chunk partials. (R12, ~84 us.)
// ---------------------------------------------------------------------------
__global__ __launch_bounds__(128, 12)
void accum_kernel(const float4* __restrict__ emb4,
                  const int* __restrict__ actions,
                  const int* __restrict__ mask)
{
    const int chunk = blockIdx.x;
    const int b     = blockIdx.y;
    const int dh    = blockIdx.z;
    const int tid   = threadIdx.x;
    const int l0    = chunk * LCHUNK;
    const int w     = tid >> 5, lane = tid & 31;

    __shared__ short s_order[LCHUNK];
    __shared__ int   s_wcnt[NA_ * NPASS * NWA_];
    __shared__ int   s_woff[NA_ * NPASS * NWA_ + 1];

    // mask is bool upcast to a 4-byte type by the harness; nonzero = True.
    int act[NPASS];
    #pragma unroll
    for (int p = 0; p < NPASS; ++p) {
        const int row = p * 128 + tid;
        int a = actions[b * L_ + l0 + row];
        int m = mask[b * L_ + l0 + row];
        act[p] = (m != 0) ? a : -1;
    }

    const unsigned lt = (1u << lane) - 1u;
    int myrank[NPASS];
    #pragma unroll
    for (int p = 0; p < NPASS; ++p) {
        myrank[p] = 0;
        #pragma unroll
        for (int aa = 0; aa < NA_; ++aa) {
            unsigned bal = __ballot_sync(0xffffffffu, act[p] == aa);
            if (lane == 0) s_wcnt[aa * (NPASS * NWA_) + p * NWA_ + w] = __popc(bal);
            if (act[p] == aa) myrank[p] = __popc(bal & lt);
        }
    }
    __syncthreads();
    if (tid == 0) {
        int acc = 0;
        #pragma unroll
        for (int q = 0; q < NA_ * NPASS * NWA_; ++q) { s_woff[q] = acc; acc += s_wcnt[q]; }
        s_woff[NA_ * NPASS * NWA_] = acc;
    }
    __syncthreads();
    #pragma unroll
    for (int p = 0; p < NPASS; ++p)
        if (act[p] >= 0)
            s_order[s_woff[act[p] * (NPASS * NWA_) + p * NWA_ + w] + myrank[p]]
                = (short)(p * 128 + tid);
    if (dh == 0 && tid < NA_)
        g_cnt[(b * NCHUNK + chunk) * NA_ + tid] =
            s_woff[(tid + 1) * (NPASS * NWA_)] - s_woff[tid * (NPASS * NWA_)];
    __syncthreads();

    const char* base = reinterpret_cast<const char*>(
        emb4 + ((size_t)b * L_ + l0) * D4_ + dh * DH4_ + tid);
    float4* outp = reinterpret_cast<float4*>(g_part)
                   + (size_t)(b * NCHUNK + chunk) * NA_ * D4_ + dh * DH4_ + tid;

    #pragma unroll 1
    for (int a = 0; a < NA_; ++a) {
        unsigned long long axy = 0ull, azw = 0ull;
        const int s = s_woff[a * (NPASS * NWA_)], e = s_woff[(a + 1) * (NPASS * NWA_)];
        int i = s;
        for (; i + 4 <= e; i += 4) {
            unsigned long long x0, y0, x1, y1, x2, y2, x3, y3;
            ldg_cs_2x64(base + (size_t)s_order[i]     * (D4_ * 16), x0, y0);
            ldg_cs_2x64(base + (size_t)s_order[i + 1] * (D4_ * 16), x1, y1);
            ldg_cs_2x64(base + (size_t)s_order[i + 2] * (D4_ * 16), x2, y2);
            ldg_cs_2x64(base + (size_t)s_order[i + 3] * (D4_ * 16), x3, y3);
            axy = addf32x2(axy, addf32x2(addf32x2(x0, x1), addf32x2(x2, x3)));
            azw = addf32x2(azw, addf32x2(addf32x2(y0, y1), addf32x2(y2, y3)));
        }
        for (; i < e; ++i) {
            unsigned long long x, y;
            ldg_cs_2x64(base + (size_t)s_order[i] * (D4_ * 16), x, y);
            axy = addf32x2(axy, x);
            azw = addf32x2(azw, y);
        }
        asm volatile("st.global.v2.u64 [%0], {%1, %2};"
                     :: "l"(outp + a * D4_), "l"(axy), "l"(azw));
    }
}

// ---------------------------------------------------------------------------
// Kernel 2: feats = (sum of 16 chunk partials) / clip(cnt,1). grid (NA,B),
// 256 threads; thread owns one float4 column. Also computes inv_cnt/seen.
// ---------------------------------------------------------------------------
__global__ __launch_bounds__(256)
void feats_kernel(float* __restrict__ dummy)
{
    const int a   = blockIdx.x;
    const int b   = blockIdx.y;
    const int tid = threadIdx.x;
    const int ba  = b * NA_ + a;

    __shared__ float s_inv;
    if (tid == 0) {
        int c = 0;
        #pragma unroll
        for (int ch = 0; ch < NCHUNK; ++ch)
            c += g_cnt[(b * NCHUNK + ch) * NA_ + a];
        const float inv = 1.0f / fmaxf((float)c, 1.0f);
        g_scal2[ba * 2 + 0] = inv;
        g_scal2[ba * 2 + 1] = (c > 0) ? 1.0f : 0.0f;
        s_inv = inv;
    }

    const float4* gp4 = reinterpret_cast<const float4*>(g_part)
                        + ((size_t)b * NCHUNK * NA_ + a) * D4_ + tid;
    // fixed grouping: (4 chunks)x4 then pairwise — deterministic
    float4 s0 = make_float4(0.f,0.f,0.f,0.f), s1 = s0, s2 = s0, s3 = s0;
    #pragma unroll
    for (int ch = 0; ch < 4; ++ch) {
        const float4 v0 = gp4[(size_t)(ch)      * NA_ * D4_];
        const float4 v1 = gp4[(size_t)(ch + 4)  * NA_ * D4_];
        const float4 v2 = gp4[(size_t)(ch + 8)  * NA_ * D4_];
        const float4 v3 = gp4[(size_t)(ch + 12) * NA_ * D4_];
        s0.x += v0.x; s0.y += v0.y; s0.z += v0.z; s0.w += v0.w;
        s1.x += v1.x; s1.y += v1.y; s1.z += v1.z; s1.w += v1.w;
        s2.x += v2.x; s2.y += v2.y; s2.z += v2.z; s2.w += v2.w;
        s3.x += v3.x; s3.y += v3.y; s3.z += v3.z; s3.w += v3.w;
    }
    __syncthreads();
    const float inv = s_inv;
    float4 r;
    r.x = ((s0.x + s1.x) + (s2.x + s3.x)) * inv;
    r.y = ((s0.y + s1.y) + (s2.y + s3.y)) * inv;
    r.z = ((s0.z + s1.z) + (s2.z + s3.z)) * inv;
    r.w = ((s0.w + s1.w) + (s2.w + s3.w)) * inv;
    reinterpret_cast<float4*>(g_feat)[ba * D4_ + tid] = r;
}

// ---------------------------------------------------------------------------
// Kernel 3: tiled partial GEMMs. grid = 384 blocks, 512 threads.
//   bx <  256: MLP1  — ds = bx&31 (32 d each), bg = bx>>5 (32 ba each)
//   bx >= 256: eMLP  — ds = idx&15 (64 d each), bg = idx>>4 (32 ba each)
// sw1 total L2 read drops 128 MB -> 4 MB (reuse across 32 ba per block).
// ---------------------------------------------------------------------------
__global__ __launch_bounds__(512)
void gemm_kernel(const float* __restrict__ sw1, const float* __restrict__ ew1)
{
    __shared__ float s_w[4096];    // 16 KB
    __shared__ float s_f[2048];    // 8 KB
    const int tid = threadIdx.x;
    const int bx  = blockIdx.x;

    if (bx < 256) {
        const int ds = bx & 31, bg = bx >> 5;
        const int d0 = ds * 32, ba0 = bg * 32;
        // weight tile [32 d][128 n]
        const float4* w4 = reinterpret_cast<const float4*>(sw1 + d0 * 128);
        #pragma unroll
        for (int t = tid; t < 1024; t += 512)
            reinterpret_cast<float4*>(s_w)[t] = w4[t];
        // feats tile [32 ba][32 d]
        #pragma unroll
        for (int t = tid; t < 1024; t += 512) {
            const int j = t >> 5, i = t & 31;
            s_f[t] = g_feat[(ba0 + j) * D_ + d0 + i];
        }
        __syncthreads();

        const int n = tid & 127, jg = tid >> 7;   // jg constant per warp
        float acc[8] = {0.f,0.f,0.f,0.f,0.f,0.f,0.f,0.f};
        #pragma unroll 4
        for (int i = 0; i < 32; ++i) {
            const float w = s_w[i * 128 + n];
            #pragma unroll
            for (int jj = 0; jj < 8; ++jj)
                acc[jj] = fmaf(s_f[(jg * 8 + jj) * 32 + i], w, acc[jj]);
        }
        #pragma unroll
        for (int jj = 0; jj < 8; ++jj)
            g_h1p[((size_t)ds * NBA + ba0 + jg * 8 + jj) * 128 + n] = acc[jj];
    } else {
        const int idx = bx - 256;
        const int ds = idx & 15, bg = idx >> 4;
        const int d0 = ds * 64, ba0 = bg * 32;
        // weight tile [64 d][64 n]
        const float4* w4 = reinterpret_cast<const float4*>(ew1 + d0 * 64);
        #pragma unroll
        for (int t = tid; t < 1024; t += 512)
            reinterpret_cast<float4*>(s_w)[t] = w4[t];
        // feats tile [32 ba][64 d]
        #pragma unroll
        for (int t = tid; t < 2048; t += 512) {
            const int j = t >> 6, i = t & 63;
            s_f[t] = g_feat[(ba0 + j) * D_ + d0 + i];
        }
        __syncthreads();

        const int n = tid & 63, jg = tid >> 6;    // jg constant per warp
        float acc[4] = {0.f,0.f,0.f,0.f};
        #pragma unroll 4
        for (int i = 0; i < 64; ++i) {
            const float w = s_w[i * 64 + n];
            #pragma unroll
            for (int jj = 0; jj < 4; ++jj)
                acc[jj] = fmaf(s_f[(jg * 4 + jj) * 64 + i], w, acc[jj]);
        }
        #pragma unroll
        for (int jj = 0; jj < 4; ++jj)
            g_ehp[((size_t)ds * NBA + ba0 + jg * 4 + jj) * 64 + n] = acc[jj];
    }
}

// ---------------------------------------------------------------------------
// Kernel 4: reduce partials (fixed ds order), relu+bias, layer 2, softmax,
// sigmoid, outputs. grid (NA, B), 512 threads.
// ---------------------------------------------------------------------------
__global__ __launch_bounds__(512)
void finish_kernel(const float* __restrict__ sb1, const float* __restrict__ sw2,
                   const float* __restrict__ sb2, const float* __restrict__ eb1,
                   const float* __restrict__ ew2, const float* __restrict__ eb2,
                   float* __restrict__ out)
{
    const int a   = blockIdx.x;
    const int b   = blockIdx.y;
    const int tid = threadIdx.x;
    const int ba  = b * NA_ + a;

    __shared__ float s_h1[128];
    __shared__ float s_eh[64];
    __shared__ float s_logit[14];
    __shared__ float s_eff[3];
    __shared__ float s_seen;

    if (tid == 511) s_seen = g_scal2[ba * 2 + 1];

    if (tid < 128) {
        float v = 0.f;
        #pragma unroll
        for (int ds = 0; ds < 32; ++ds)
            v += g_h1p[((size_t)ds * NBA + ba) * 128 + tid];
        s_h1[tid] = fmaxf(v + sb1[tid], 0.0f);
    } else if (tid < 192) {
        const int n = tid - 128;
        float v = 0.f;
        #pragma unroll
        for (int ds = 0; ds < 16; ++ds)
            v += g_ehp[((size_t)ds * NBA + ba) * 64 + n];
        s_eh[n] = fmaxf(v + eb1[n], 0.0f);
    }
    __syncthreads();

    // ---- layer 2: warp-per-output ----
    {
        const int w = tid >> 5, lane = tid & 31;
        if (w < 14) {
            float acc = 0.f;
            #pragma unroll
            for (int k = lane; k < 128; k += 32)
                acc = fmaf(s_h1[k], sw2[k * 14 + w], acc);
            #pragma unroll
            for (int off = 16; off > 0; off >>= 1)
                acc += __shfl_down_sync(0xffffffffu, acc, off);
            if (lane == 0) s_logit[w] = acc + sb2[w];
        } else if (w == 14) {
            #pragma unroll
            for (int j = 0; j < 3; ++j) {
                float acc = fmaf(s_eh[lane], ew2[lane * 3 + j],
                                 s_eh[lane + 32] * ew2[(lane + 32) * 3 + j]);
                #pragma unroll
                for (int off = 16; off > 0; off >>= 1)
                    acc += __shfl_down_sync(0xffffffffu, acc, off);
                if (lane == 0) s_eff[j] = acc + eb2[j];
            }
        }
    }
    __syncthreads();

    // Output layout (flat float32, reference tuple order):
    //   [0,512)     shift (B,8,2)   [512,2304)  dx_logits (B,8,7)
    //   [2304,4096) dy_logits       [4096,4352) sig(e0)*seen
    //   [4352,4608) sig(e1)*seen    [4608,4864) e2*seen
    const float seen = s_seen;

    if (tid < 7)              out[512  + ba * 7 + tid]       = s_logit[tid];
    if (tid >= 7 && tid < 14) out[2304 + ba * 7 + (tid - 7)] = s_logit[tid];

    if (tid == 0) {
        const float bins[7] = {-16.f, -8.f, -4.f, 0.f, 4.f, 8.f, 16.f};
        #pragma unroll
        for (int h = 0; h < 2; ++h) {
            const float* lg = &s_logit[h * 7];
            float mx = lg[0];
            #pragma unroll
            for (int j = 1; j < 7; ++j) mx = fmaxf(mx, lg[j]);
            float den = 0.f, num = 0.f;
            #pragma unroll
            for (int j = 0; j < 7; ++j) {
                const float e = __expf(lg[j] - mx);
                den += e;
                num += e * bins[j];
            }
            out[ba * 2 + h] = (num / den) * seen;
        }
        out[4096 + ba] = (1.0f / (1.0f + __expf(-s_eff[0]))) * seen;
        out[4352 + ba] = (1.0f / (1.0f + __expf(-s_eff[1]))) * seen;
        out[4608 + ba] = s_eff[2] * seen;
    }
}

// ---------------------------------------------------------------------------
extern "C" void kernel_launch(void* const* d_in, const int* in_sizes, int n_in,
                              void* d_out, int out_size)
{
    const float4* emb4 = (const float4*)d_in[0];
    const int*    act  = (const int*)d_in[1];
    const int*    mask = (const int*)d_in[2];
    const float* sw1 = (const float*)d_in[3];
    const float* sb1 = (const float*)d_in[4];
    const float* sw2 = (const float*)d_in[5];
    const float* sb2 = (const float*)d_in[6];
    const float* ew1 = (const float*)d_in[7];
    const float* eb1 = (const float*)d_in[8];
    const float* ew2 = (const float*)d_in[9];
    const float* eb2 = (const float*)d_in[10];
    float* out = (float*)d_out;

    accum_kernel<<<dim3(NCHUNK, B_, 2), 128>>>(emb4, act, mask);
    feats_kernel<<<dim3(NA_, B_), 256>>>(out);
    gemm_kernel<<<384, 512>>>(sw1, ew1);
    finish_kernel<<<dim3(NA_, B_), 512>>>(sb1, sw2, sb2, eb1, ew2, eb2, out);
}

// round 15
// speedup vs baseline: 1.0009x; 1.0009x over previous
#include <cuda_runtime.h>
#include <math.h>

#define B_  32
#define L_  4096
#define D_  1024
#define D4_ (D_ / 4)           // 256 float4 per row
#define NA_ 8
#define NCHUNK 16
#define LCHUNK (L_ / NCHUNK)   // 256
#define NWA_ 4                 // warps per accum block (128 threads)
#define NPASS 2                // row passes (256 rows / 128 threads)
#define DH4_ 128               // float4 columns per D-half
#define NBA 256                // B_*NA_

// Scratch (device globals; no allocation).
__device__ float g_part[B_ * NCHUNK * NA_ * D_];   // 16.8 MB
__device__ int   g_cnt [B_ * NCHUNK * NA_];
__device__ float g_h1p[32 * NBA * 128];            // 4 MB   [ds][ba][n]
__device__ float g_ehp[16 * NBA * 64];             // 1 MB   [ds][ba][n]

// 16-byte streaming load as two 64-bit halves (each = packed f32x2).
__device__ __forceinline__ void ldg_cs_2x64(const void* p,
                                            unsigned long long& x,
                                            unsigned long long& y)
{
    asm volatile("ld.global.cs.v2.u64 {%0, %1}, [%2];"
                 : "=l"(x), "=l"(y) : "l"(p));
}
__device__ __forceinline__ unsigned long long addf32x2(unsigned long long a,
                                                       unsigned long long b)
{
    unsigned long long r;
    asm("add.rn.f32x2 %0, %1, %2;" : "=l"(r) : "l"(a), "l"(b));
    return r;
}

// Deterministic 16-chunk feats sum for one (ba, d): fixed (4x4) grouping.
__device__ __forceinline__ float feats_sum16(int ba, int d)
{
    const int b = ba >> 3, a = ba & 7;
    const float* p = g_part + ((size_t)(b * NCHUNK) * NA_ + a) * D_ + d;
    const size_t str = (size_t)NA_ * D_;
    float s0 = 0.f, s1 = 0.f, s2 = 0.f, s3 = 0.f;
    #pragma unroll
    for (int ch = 0; ch < 4; ++ch) {
        s0 += p[(size_t)(ch)      * str];
        s1 += p[(size_t)(ch + 4)  * str];
        s2 += p[(size_t)(ch + 8)  * str];
        s3 += p[(size_t)(ch + 12) * str];
    }
    return (s0 + s1) + (s2 + s3);
}

// ---------------------------------------------------------------------------
// Kernel 1: masked segmented sum into per-chunk partials. (R12, ~84 us.)
// ---------------------------------------------------------------------------
__global__ __launch_bounds__(128, 12)
void accum_kernel(const float4* __restrict__ emb4,
                  const int* __restrict__ actions,
                  const int* __restrict__ mask)
{
    const int chunk = blockIdx.x;
    const int b     = blockIdx.y;
    const int dh    = blockIdx.z;
    const int tid   = threadIdx.x;
    const int l0    = chunk * LCHUNK;
    const int w     = tid >> 5, lane = tid & 31;

    __shared__ short s_order[LCHUNK];
    __shared__ int   s_wcnt[NA_ * NPASS * NWA_];
    __shared__ int   s_woff[NA_ * NPASS * NWA_ + 1];

    // mask is bool upcast to a 4-byte type by the harness; nonzero = True.
    int act[NPASS];
    #pragma unroll
    for (int p = 0; p < NPASS; ++p) {
        const int row = p * 128 + tid;
        int a = actions[b * L_ + l0 + row];
        int m = mask[b * L_ + l0 + row];
        act[p] = (m != 0) ? a : -1;
    }

    const unsigned lt = (1u << lane) - 1u;
    int myrank[NPASS];
    #pragma unroll
    for (int p = 0; p < NPASS; ++p) {
        myrank[p] = 0;
        #pragma unroll
        for (int aa = 0; aa < NA_; ++aa) {
            unsigned bal = __ballot_sync(0xffffffffu, act[p] == aa);
            if (lane == 0) s_wcnt[aa * (NPASS * NWA_) + p * NWA_ + w] = __popc(bal);
            if (act[p] == aa) myrank[p] = __popc(bal & lt);
        }
    }
    __syncthreads();
    if (tid == 0) {
        int acc = 0;
        #pragma unroll
        for (int q = 0; q < NA_ * NPASS * NWA_; ++q) { s_woff[q] = acc; acc += s_wcnt[q]; }
        s_woff[NA_ * NPASS * NWA_] = acc;
    }
    __syncthreads();
    #pragma unroll
    for (int p = 0; p < NPASS; ++p)
        if (act[p] >= 0)
            s_order[s_woff[act[p] * (NPASS * NWA_) + p * NWA_ + w] + myrank[p]]
                = (short)(p * 128 + tid);
    if (dh == 0 && tid < NA_)
        g_cnt[(b * NCHUNK + chunk) * NA_ + tid] =
            s_woff[(tid + 1) * (NPASS * NWA_)] - s_woff[tid * (NPASS * NWA_)];
    __syncthreads();

    const char* base = reinterpret_cast<const char*>(
        emb4 + ((size_t)b * L_ + l0) * D4_ + dh * DH4_ + tid);
    float4* outp = reinterpret_cast<float4*>(g_part)
                   + (size_t)(b * NCHUNK + chunk) * NA_ * D4_ + dh * DH4_ + tid;

    #pragma unroll 1
    for (int a = 0; a < NA_; ++a) {
        unsigned long long axy = 0ull, azw = 0ull;
        const int s = s_woff[a * (NPASS * NWA_)], e = s_woff[(a + 1) * (NPASS * NWA_)];
        int i = s;
        for (; i + 4 <= e; i += 4) {
            unsigned long long x0, y0, x1, y1, x2, y2, x3, y3;
            ldg_cs_2x64(base + (size_t)s_order[i]     * (D4_ * 16), x0, y0);
            ldg_cs_2x64(base + (size_t)s_order[i + 1] * (D4_ * 16), x1, y1);
            ldg_cs_2x64(base + (size_t)s_order[i + 2] * (D4_ * 16), x2, y2);
            ldg_cs_2x64(base + (size_t)s_order[i + 3] * (D4_ * 16), x3, y3);
            axy = addf32x2(axy, addf32x2(addf32x2(x0, x1), addf32x2(x2, x3)));
            azw = addf32x2(azw, addf32x2(addf32x2(y0, y1), addf32x2(y2, y3)));
        }
        for (; i < e; ++i) {
            unsigned long long x, y;
            ldg_cs_2x64(base + (size_t)s_order[i] * (D4_ * 16), x, y);
            axy = addf32x2(axy, x);
            azw = addf32x2(azw, y);
        }
        asm volatile("st.global.v2.u64 [%0], {%1, %2};"
                     :: "l"(outp + a * D4_), "l"(axy), "l"(azw));
    }
}

// ---------------------------------------------------------------------------
// Kernel 2: tiled partial GEMMs with inline feats computation.
// grid = 384 blocks, 512 threads.
//   bx <  256: MLP1 — ds = bx&31 (d-slice of 32), bg = bx>>5 (32 ba)
//   bx >= 256: eMLP — ds = idx&15 (d-slice of 64), bg = idx>>4 (32 ba)
// Each flavor's (ds, bg) tiles partition (ba, d), so g_part is re-read
// exactly once per flavor (L2-hot). Weight traffic: sw1 4 MB, ew1 1 MB.
// ---------------------------------------------------------------------------
__global__ __launch_bounds__(512)
void gemm_kernel(const float* __restrict__ sw1, const float* __restrict__ ew1)
{
    __shared__ float s_w[4096];    // 16 KB weight tile
    __shared__ float s_f[2048];    // 8 KB feats tile
    __shared__ float s_inv[32];
    const int tid = threadIdx.x;
    const int bx  = blockIdx.x;

    if (bx < 256) {
        const int ds = bx & 31, bg = bx >> 5;
        const int d0 = ds * 32, ba0 = bg * 32;

        // weight tile [32 d][128 n]
        const float4* w4 = reinterpret_cast<const float4*>(sw1 + d0 * 128);
        #pragma unroll
        for (int t = tid; t < 1024; t += 512)
            reinterpret_cast<float4*>(s_w)[t] = w4[t];
        // inv counts for the 32 ba
        if (tid < 32) {
            const int ba = ba0 + tid, b = ba >> 3, a = ba & 7;
            int c = 0;
            #pragma unroll
            for (int ch = 0; ch < NCHUNK; ++ch)
                c += g_cnt[(b * NCHUNK + ch) * NA_ + a];
            s_inv[tid] = 1.0f / fmaxf((float)c, 1.0f);
        }
        // feats tile raw sums [32 ba][32 d]; 2 elements per thread
        const int j0 = tid >> 5, i0 = tid & 31;
        const float r0 = feats_sum16(ba0 + j0,      d0 + i0);
        const float r1 = feats_sum16(ba0 + j0 + 16, d0 + i0);
        __syncthreads();                 // s_inv ready
        s_f[j0 * 32 + i0]        = r0 * s_inv[j0];
        s_f[(j0 + 16) * 32 + i0] = r1 * s_inv[j0 + 16];
        __syncthreads();

        const int n = tid & 127, jg = tid >> 7;   // jg constant per warp
        float acc[8] = {0.f,0.f,0.f,0.f,0.f,0.f,0.f,0.f};
        #pragma unroll 4
        for (int i = 0; i < 32; ++i) {
            const float w = s_w[i * 128 + n];
            #pragma unroll
            for (int jj = 0; jj < 8; ++jj)
                acc[jj] = fmaf(s_f[(jg * 8 + jj) * 32 + i], w, acc[jj]);
        }
        #pragma unroll
        for (int jj = 0; jj < 8; ++jj)
            g_h1p[((size_t)ds * NBA + ba0 + jg * 8 + jj) * 128 + n] = acc[jj];
    } else {
        const int idx = bx - 256;
        const int ds = idx & 15, bg = idx >> 4;
        const int d0 = ds * 64, ba0 = bg * 32;

        // weight tile [64 d][64 n]
        const float4* w4 = reinterpret_cast<const float4*>(ew1 + d0 * 64);
        #pragma unroll
        for (int t = tid; t < 1024; t += 512)
            reinterpret_cast<float4*>(s_w)[t] = w4[t];
        if (tid < 32) {
            const int ba = ba0 + tid, b = ba >> 3, a = ba & 7;
            int c = 0;
            #pragma unroll
            for (int ch = 0; ch < NCHUNK; ++ch)
                c += g_cnt[(b * NCHUNK + ch) * NA_ + a];
            s_inv[tid] = 1.0f / fmaxf((float)c, 1.0f);
        }
        // feats tile raw sums [32 ba][64 d]; 4 elements per thread
        const int j0 = tid >> 6, i0 = tid & 63;      // j0 in 0..7
        float r[4];
        #pragma unroll
        for (int k = 0; k < 4; ++k)
            r[k] = feats_sum16(ba0 + j0 + k * 8, d0 + i0);
        __syncthreads();
        #pragma unroll
        for (int k = 0; k < 4; ++k)
            s_f[(j0 + k * 8) * 64 + i0] = r[k] * s_inv[j0 + k * 8];
        __syncthreads();

        const int n = tid & 63, jg = tid >> 6;       // jg constant per warp
        float acc[4] = {0.f,0.f,0.f,0.f};
        #pragma unroll 4
        for (int i = 0; i < 64; ++i) {
            const float w = s_w[i * 64 + n];
            #pragma unroll
            for (int jj = 0; jj < 4; ++jj)
                acc[jj] = fmaf(s_f[(jg * 4 + jj) * 64 + i], w, acc[jj]);
        }
        #pragma unroll
        for (int jj = 0; jj < 4; ++jj)
            g_ehp[((size_t)ds * NBA + ba0 + jg * 4 + jj) * 64 + n] = acc[jj];
    }
}

// ---------------------------------------------------------------------------
// Kernel 3: parallel reduce of partials, relu+bias, layer 2, softmax,
// sigmoid, outputs. grid (NA, B), 512 threads — ALL threads reduce.
// ---------------------------------------------------------------------------
__global__ __launch_bounds__(512)
void finish_kernel(const float* __restrict__ sb1, const float* __restrict__ sw2,
                   const float* __restrict__ sb2, const float* __restrict__ eb1,
                   const float* __restrict__ ew2, const float* __restrict__ eb2,
                   float* __restrict__ out)
{
    const int a   = blockIdx.x;
    const int b   = blockIdx.y;
    const int tid = threadIdx.x;
    const int ba  = b * NA_ + a;

    __shared__ float s_red [512];   // h1 partials [q][n]
    __shared__ float s_red2[512];   // eh partials [q][n]
    __shared__ float s_h1[128];
    __shared__ float s_eh[64];
    __shared__ float s_logit[14];
    __shared__ float s_eff[3];
    __shared__ float s_seen;

    if (tid == 480) {
        int c = 0;
        #pragma unroll
        for (int ch = 0; ch < NCHUNK; ++ch)
            c += g_cnt[(b * NCHUNK + ch) * NA_ + a];
        s_seen = (c > 0) ? 1.0f : 0.0f;
    }

    // h1 partials: 4 threads per neuron, 8 ds each
    {
        const int n = tid & 127, q = tid >> 7;       // q in 0..3
        float v = 0.f;
        #pragma unroll
        for (int k = 0; k < 8; ++k)
            v += g_h1p[((size_t)(q * 8 + k) * NBA + ba) * 128 + n];
        s_red[q * 128 + n] = v;
    }
    // eh partials: 8 threads per neuron, 2 ds each
    {
        const int n = tid & 63, q = tid >> 6;        // q in 0..7
        float v = g_ehp[((size_t)(q * 2) * NBA + ba) * 64 + n]
                + g_ehp[((size_t)(q * 2 + 1) * NBA + ba) * 64 + n];
        s_red2[q * 64 + n] = v;
    }
    __syncthreads();

    if (tid < 128) {
        float v = (s_red[tid] + s_red[128 + tid])
                + (s_red[256 + tid] + s_red[384 + tid]);
        s_h1[tid] = fmaxf(v + sb1[tid], 0.0f);
    } else if (tid < 192) {
        const int n = tid - 128;
        float v = ((s_red2[n] + s_red2[64 + n]) + (s_red2[128 + n] + s_red2[192 + n]))
                + ((s_red2[256 + n] + s_red2[320 + n]) + (s_red2[384 + n] + s_red2[448 + n]));
        s_eh[n] = fmaxf(v + eb1[n], 0.0f);
    }
    __syncthreads();

    // ---- layer 2: warp-per-output ----
    {
        const int w = tid >> 5, lane = tid & 31;
        if (w < 14) {
            float acc = 0.f;
            #pragma unroll
            for (int k = lane; k < 128; k += 32)
                acc = fmaf(s_h1[k], sw2[k * 14 + w], acc);
            #pragma unroll
            for (int off = 16; off > 0; off >>= 1)
                acc += __shfl_down_sync(0xffffffffu, acc, off);
            if (lane == 0) s_logit[w] = acc + sb2[w];
        } else if (w == 14) {
            #pragma unroll
            for (int j = 0; j < 3; ++j) {
                float acc = fmaf(s_eh[lane], ew2[lane * 3 + j],
                                 s_eh[lane + 32] * ew2[(lane + 32) * 3 + j]);
                #pragma unroll
                for (int off = 16; off > 0; off >>= 1)
                    acc += __shfl_down_sync(0xffffffffu, acc, off);
                if (lane == 0) s_eff[j] = acc + eb2[j];
            }
        }
    }
    __syncthreads();

    // Output layout (flat float32, reference tuple order):
    //   [0,512)     shift (B,8,2)   [512,2304)  dx_logits (B,8,7)
    //   [2304,4096) dy_logits       [4096,4352) sig(e0)*seen
    //   [4352,4608) sig(e1)*seen    [4608,4864) e2*seen
    const float seen = s_seen;

    if (tid < 7)              out[512  + ba * 7 + tid]       = s_logit[tid];
    if (tid >= 7 && tid < 14) out[2304 + ba * 7 + (tid - 7)] = s_logit[tid];

    if (tid == 0) {
        const float bins[7] = {-16.f, -8.f, -4.f, 0.f, 4.f, 8.f, 16.f};
        #pragma unroll
        for (int h = 0; h < 2; ++h) {
            const float* lg = &s_logit[h * 7];
            float mx = lg[0];
            #pragma unroll
            for (int j = 1; j < 7; ++j) mx = fmaxf(mx, lg[j]);
            float den = 0.f, num = 0.f;
            #pragma unroll
            for (int j = 0; j < 7; ++j) {
                const float e = __expf(lg[j] - mx);
                den += e;
                num += e * bins[j];
            }
            out[ba * 2 + h] = (num / den) * seen;
        }
        out[4096 + ba] = (1.0f / (1.0f + __expf(-s_eff[0]))) * seen;
        out[4352 + ba] = (1.0f / (1.0f + __expf(-s_eff[1]))) * seen;
        out[4608 + ba] = s_eff[2] * seen;
    }
}

// ---------------------------------------------------------------------------
extern "C" void kernel_launch(void* const* d_in, const int* in_sizes, int n_in,
                              void* d_out, int out_size)
{
    const float4* emb4 = (const float4*)d_in[0];
    const int*    act  = (const int*)d_in[1];
    const int*    mask = (const int*)d_in[2];
    const float* sw1 = (const float*)d_in[3];
    const float* sb1 = (const float*)d_in[4];
    const float* sw2 = (const float*)d_in[5];
    const float* sb2 = (const float*)d_in[6];
    const float* ew1 = (const float*)d_in[7];
    const float* eb1 = (const float*)d_in[8];
    const float* ew2 = (const float*)d_in[9];
    const float* eb2 = (const float*)d_in[10];
    float* out = (float*)d_out;

    accum_kernel<<<dim3(NCHUNK, B_, 2), 128>>>(emb4, act, mask);
    gemm_kernel<<<384, 512>>>(sw1, ew1);
    finish_kernel<<<dim3(NA_, B_), 512>>>(sb1, sw2, sb2, eb1, ew2, eb2, out);
}